// round 2
// baseline (speedup 1.0000x reference)
#include <cuda_runtime.h>

// LTU_5918464934238: binary-threshold GEMV, warp-per-row.
// out[i] = (W[i]·x + count(W[i]<0) < 2457.6) ? 0 : 1
//
// HBM-bound (128 MB stream of W). Each warp owns a row: continuous LDG.128
// stream (unroll 8), no barriers inside the row loop, shuffle-only reduce.

#define LTU_THREADS 256
#define LTU_WARPS   (LTU_THREADS / 32)
#define LTU_VECS    1024                 // 4096 floats / 4 per row

__global__ __launch_bounds__(LTU_THREADS)
void ltu_kernel(const float* __restrict__ x,
                const float* __restrict__ W,
                float* __restrict__ out,
                int rows)
{
    __shared__ float4 xs[LTU_VECS];      // 16 KB, staged once per block

    const float4* xv = reinterpret_cast<const float4*>(x);
    for (int i = threadIdx.x; i < LTU_VECS; i += LTU_THREADS)
        xs[i] = xv[i];
    __syncthreads();                     // the ONLY block barrier

    const int lane  = threadIdx.x & 31;
    const int warp  = threadIdx.x >> 5;
    const int gwarp = blockIdx.x * LTU_WARPS + warp;
    const int nwarp = gridDim.x * LTU_WARPS;

    for (int row = gwarp; row < rows; row += nwarp) {
        const float4* Wr = reinterpret_cast<const float4*>(W)
                           + (size_t)row * LTU_VECS;

        float4 acc = make_float4(0.f, 0.f, 0.f, 0.f);  // fma pipe
        unsigned cx = 0, cy = 0, cz = 0, cw = 0;       // alu pipe (sign counts)

        #pragma unroll 8
        for (int j = 0; j < 32; j++) {
            const int idx = lane + j * 32;             // 512B coalesced per warp
            const float4 w = Wr[idx];
            const float4 v = xs[idx];
            acc.x = fmaf(w.x, v.x, acc.x);
            acc.y = fmaf(w.y, v.y, acc.y);
            acc.z = fmaf(w.z, v.z, acc.z);
            acc.w = fmaf(w.w, v.w, acc.w);
            cx += __float_as_uint(w.x) >> 31;
            cy += __float_as_uint(w.y) >> 31;
            cz += __float_as_uint(w.z) >> 31;
            cw += __float_as_uint(w.w) >> 31;
        }

        float t = (acc.x + acc.y) + (acc.z + acc.w)
                + (float)(cx + cy + cz + cw);

        // warp reduce — no smem, no barriers
        #pragma unroll
        for (int o = 16; o > 0; o >>= 1)
            t += __shfl_xor_sync(0xffffffffu, t, o);

        if (lane == 0) {
            const float tau_base = 0.6f * 4096.0f;     // 2457.60009765625
            out[row] = (t < tau_base) ? 0.0f : 1.0f;
        }
    }
}

extern "C" void kernel_launch(void* const* d_in, const int* in_sizes, int n_in,
                              void* d_out, int out_size)
{
    const float* x = (const float*)d_in[0];
    const float* W = (const float*)d_in[1];
    if (n_in >= 2 && in_sizes[0] > in_sizes[1]) {
        x = (const float*)d_in[1];
        W = (const float*)d_in[0];
    }
    float* out = (float*)d_out;
    const int rows = out_size;            // 8192

    // 512 blocks * 8 warps = 4096 warps -> exactly 2 rows per warp.
    const int grid = 512;
    ltu_kernel<<<grid, LTU_THREADS>>>(x, W, out, rows);
}

// round 3
// speedup vs baseline: 1.4640x; 1.4640x over previous
#include <cuda_runtime.h>

// LTU_5918464934238: binary-threshold GEMV, one block per row.
// out[i] = (W[i]·x + count(W[i]<0) < 2457.6) ? 0 : 1
//
// Pure 128 MB stream of W. grid=8192 (block per row): no row loop, no
// x-staging barrier. x (16 KB) is L1-resident after the first block per SM.
// Each thread front-batches 8 LDG.128 (4 W + 4 x) -> MLP_p1=8; reduce only
// at block end, hidden by concurrent blocks on the same SM.

#define LTU_THREADS 256
#define LTU_VECS    1024                 // 4096 floats / 4 per row

__global__ __launch_bounds__(LTU_THREADS)
void ltu_kernel(const float* __restrict__ x,
                const float* __restrict__ W,
                float* __restrict__ out)
{
    __shared__ float wsum[LTU_THREADS / 32];

    const int tid = threadIdx.x;
    const int row = blockIdx.x;

    const float4* __restrict__ Wr =
        reinterpret_cast<const float4*>(W) + (size_t)row * LTU_VECS;
    const float4* __restrict__ xv = reinterpret_cast<const float4*>(x);

    // Front-batched independent loads: 4x W (DRAM stream) + 4x x (L1 hit).
    const float4 w0 = Wr[tid];
    const float4 w1 = Wr[tid + 256];
    const float4 w2 = Wr[tid + 512];
    const float4 w3 = Wr[tid + 768];
    const float4 v0 = xv[tid];
    const float4 v1 = xv[tid + 256];
    const float4 v2 = xv[tid + 512];
    const float4 v3 = xv[tid + 768];

    // fma pipe: dot products (4 independent accumulators)
    float a0 = 0.f, a1 = 0.f, a2 = 0.f, a3 = 0.f;
    a0 = fmaf(w0.x, v0.x, a0); a1 = fmaf(w0.y, v0.y, a1);
    a2 = fmaf(w0.z, v0.z, a2); a3 = fmaf(w0.w, v0.w, a3);
    a0 = fmaf(w1.x, v1.x, a0); a1 = fmaf(w1.y, v1.y, a1);
    a2 = fmaf(w1.z, v1.z, a2); a3 = fmaf(w1.w, v1.w, a3);
    a0 = fmaf(w2.x, v2.x, a0); a1 = fmaf(w2.y, v2.y, a1);
    a2 = fmaf(w2.z, v2.z, a2); a3 = fmaf(w2.w, v2.w, a3);
    a0 = fmaf(w3.x, v3.x, a0); a1 = fmaf(w3.y, v3.y, a1);
    a2 = fmaf(w3.z, v3.z, a2); a3 = fmaf(w3.w, v3.w, a3);

    // alu pipe: negative-weight count via sign bits
    unsigned c =
        (__float_as_uint(w0.x) >> 31) + (__float_as_uint(w0.y) >> 31) +
        (__float_as_uint(w0.z) >> 31) + (__float_as_uint(w0.w) >> 31) +
        (__float_as_uint(w1.x) >> 31) + (__float_as_uint(w1.y) >> 31) +
        (__float_as_uint(w1.z) >> 31) + (__float_as_uint(w1.w) >> 31) +
        (__float_as_uint(w2.x) >> 31) + (__float_as_uint(w2.y) >> 31) +
        (__float_as_uint(w2.z) >> 31) + (__float_as_uint(w2.w) >> 31) +
        (__float_as_uint(w3.x) >> 31) + (__float_as_uint(w3.y) >> 31) +
        (__float_as_uint(w3.z) >> 31) + (__float_as_uint(w3.w) >> 31);

    float t = (a0 + a1) + (a2 + a3) + (float)c;

    // intra-warp reduce
    #pragma unroll
    for (int o = 16; o > 0; o >>= 1)
        t += __shfl_xor_sync(0xffffffffu, t, o);

    const int lane = tid & 31;
    const int warp = tid >> 5;
    if (lane == 0) wsum[warp] = t;
    __syncthreads();

    if (warp == 0) {
        float s = (lane < (LTU_THREADS / 32)) ? wsum[lane] : 0.0f;
        #pragma unroll
        for (int o = (LTU_THREADS / 64); o > 0; o >>= 1)
            s += __shfl_xor_sync(0xffffffffu, s, o);
        if (lane == 0) {
            const float tau_base = 0.6f * 4096.0f;   // 2457.60009765625
            out[row] = (s < tau_base) ? 0.0f : 1.0f;
        }
    }
}

extern "C" void kernel_launch(void* const* d_in, const int* in_sizes, int n_in,
                              void* d_out, int out_size)
{
    const float* x = (const float*)d_in[0];
    const float* W = (const float*)d_in[1];
    if (n_in >= 2 && in_sizes[0] > in_sizes[1]) {
        x = (const float*)d_in[1];
        W = (const float*)d_in[0];
    }
    float* out = (float*)d_out;
    const int rows = out_size;            // 8192

    ltu_kernel<<<rows, LTU_THREADS>>>(x, W, out);
}